// round 17
// baseline (speedup 1.0000x reference)
#include <cuda_runtime.h>
#include <cuda_fp16.h>
#include <math.h>
#include <stdint.h>

#define BB 8
#define SS 2048
#define DD 768
#define BS (BB * SS)

// Scratch (no cudaMalloc allowed)
__device__ __half g_Zh[BS * DD];               // fp16 Z
__device__ __half g_Wh[3 * DD * DD];           // fp16 Wq,Wk,Wv (contig)
__device__ __half g_Q[BS * DD];
__device__ __half g_K[BS * DD];
__device__ __half g_Vt[BS * DD];               // layout [e][b*s] (ld = BS)
__device__ __half g_P[(long long)BB * SS * SS]; // UNNORMALIZED exp(logit), fp16
__device__ float  g_RInv[BS];                  // 1 / rowsum(exp)

// 2-stage pipeline, tiles [128 rows][72 halfs] (Kc=64 + 8 pad halfs), conflict-free
#define STAGE_HB (128 * 72 * 2)
#define SMEM_BYTES (4 * STAGE_HB)              // 72KB

__device__ __forceinline__ void mma_f16(float c[4],
                                        uint32_t a0, uint32_t a1, uint32_t a2, uint32_t a3,
                                        uint32_t b0, uint32_t b1) {
    asm volatile(
        "mma.sync.aligned.m16n8k16.row.col.f32.f16.f16.f32 "
        "{%0,%1,%2,%3}, {%4,%5,%6,%7}, {%8,%9}, {%0,%1,%2,%3};\n"
        : "+f"(c[0]), "+f"(c[1]), "+f"(c[2]), "+f"(c[3])
        : "r"(a0), "r"(a1), "r"(a2), "r"(a3), "r"(b0), "r"(b1));
}

__device__ __forceinline__ void ldsm4(uint32_t& r0, uint32_t& r1, uint32_t& r2, uint32_t& r3,
                                      uint32_t addr) {
    asm volatile("ldmatrix.sync.aligned.m8n8.x4.shared.b16 {%0,%1,%2,%3}, [%4];\n"
                 : "=r"(r0), "=r"(r1), "=r"(r2), "=r"(r3) : "r"(addr));
}

__device__ __forceinline__ void cpasync16(uint32_t dst, const void* src) {
    asm volatile("cp.async.cg.shared.global [%0], [%1], 16;\n" :: "r"(dst), "l"(src));
}

// ---------------------------------------------------------------------------
// fp16 tensor-core NT GEMM: C = post( scale*(A @ B^T) + bias )
//   post: optional exp() (EXPO) and/or per-M-row multiply by rowinv (RSC).
//   A:[M,K] ld=lda halfs, B:[N,K] ld=ldb halfs (K-contig), C:[M,N] ld=ldc.
// 128x128 block tile, Kc=64 (4 K=16 slabs/barrier), 2-stage cp.async, 256 thr,
// warp tile 32x64 = 2x8 m16n8k16, B-fragments double-buffered across slabs.
// BROW: bias indexed by M-row (transposed-V projection) else by N-col.
// HOUT: store half (else float). RSC rowinv stride per batch = SS.
// ---------------------------------------------------------------------------
template <bool BROW, bool HOUT, bool EXPO, bool RSC>
__global__ void __launch_bounds__(256, 2)
gemm_h(const __half* __restrict__ A, const __half* __restrict__ Bm,
       const float* __restrict__ bias, const float* __restrict__ rowinv,
       void* __restrict__ Cv,
       int K, int lda, int ldb, int ldc,
       long long sA, long long sB, long long sC, float scale)
{
    extern __shared__ __align__(16) char smem[];

    const int b = blockIdx.z;
    A  += (long long)b * sA;
    Bm += (long long)b * sB;
    if (RSC) rowinv += (long long)b * SS;
    __half* Ch = HOUT ? ((__half*)Cv + (long long)b * sC) : nullptr;
    float*  Cf = HOUT ? nullptr : ((float*)Cv + (long long)b * sC);

    const int tid   = threadIdx.x;
    const int lane  = tid & 31;
    const int warp  = tid >> 5;
    const int warpM = warp & 3;
    const int warpN = warp >> 2;
    const int grp   = lane >> 2;
    const int qid   = lane & 3;
    const int m0    = blockIdx.y * 128;
    const int n0    = blockIdx.x * 128;

    const int local = lane & 7;
    const int sel   = lane >> 3;
    const int rowA = warpM * 32 + ((sel & 1) << 3) + local;
    const int kcA  = (sel >> 1) << 3;
    const int rowB = warpN * 64 + ((sel >> 1) << 3) + local;
    const int kcB  = (sel & 1) << 3;

    const uint32_t as_base = (uint32_t)__cvta_generic_to_shared(smem);
    const uint32_t bs_base = as_base + 2 * STAGE_HB;

    float acc[2][8][4];
#pragma unroll
    for (int mt = 0; mt < 2; mt++)
#pragma unroll
        for (int nt = 0; nt < 8; nt++)
#pragma unroll
            for (int r = 0; r < 4; r++) acc[mt][nt][r] = 0.f;

    auto load_stage = [&](int k0, int s) {
#pragma unroll
        for (int i = 0; i < 4; i++) {
            int slot = tid + i * 256;
            int row  = slot >> 3;
            int j    = slot & 7;
            cpasync16(as_base + s * STAGE_HB + (row * 72 + j * 8) * 2,
                      &A[(long long)(m0 + row) * lda + k0 + j * 8]);
            cpasync16(bs_base + s * STAGE_HB + (row * 72 + j * 8) * 2,
                      &Bm[(long long)(n0 + row) * ldb + k0 + j * 8]);
        }
        asm volatile("cp.async.commit_group;\n" ::);
    };

    const int NK = K >> 6;
    load_stage(0, 0);

    for (int it = 0; it < NK; it++) {
        if (it + 1 < NK) {
            load_stage((it + 1) << 6, (it + 1) & 1);
            asm volatile("cp.async.wait_group 1;\n" ::);
        } else {
            asm volatile("cp.async.wait_group 0;\n" ::);
        }
        __syncthreads();

        const uint32_t as_s = as_base + (it & 1) * STAGE_HB;
        const uint32_t bs_s = bs_base + (it & 1) * STAGE_HB;

        uint32_t bf[2][4][4];
#pragma unroll
        for (int p = 0; p < 4; p++) {
            uint32_t addr = bs_s + (((rowB + p * 16) * 72) + kcB) * 2;
            ldsm4(bf[0][p][0], bf[0][p][1], bf[0][p][2], bf[0][p][3], addr);
        }

#pragma unroll
        for (int ks = 0; ks < 4; ks++) {
            const int cur = ks & 1, nxt = cur ^ 1;
            const int kb  = ks * 16;

            uint32_t af[2][4];
#pragma unroll
            for (int mt = 0; mt < 2; mt++) {
                uint32_t addr = as_s + (((rowA + mt * 16) * 72) + kb + kcA) * 2;
                ldsm4(af[mt][0], af[mt][1], af[mt][2], af[mt][3], addr);
            }
            if (ks < 3) {
#pragma unroll
                for (int p = 0; p < 4; p++) {
                    uint32_t addr = bs_s + (((rowB + p * 16) * 72) + kb + 16 + kcB) * 2;
                    ldsm4(bf[nxt][p][0], bf[nxt][p][1], bf[nxt][p][2], bf[nxt][p][3], addr);
                }
            }
#pragma unroll
            for (int p = 0; p < 4; p++) {
#pragma unroll
                for (int mt = 0; mt < 2; mt++) {
                    mma_f16(acc[mt][2 * p],     af[mt][0], af[mt][1], af[mt][2], af[mt][3],
                            bf[cur][p][0], bf[cur][p][1]);
                    mma_f16(acc[mt][2 * p + 1], af[mt][0], af[mt][1], af[mt][2], af[mt][3],
                            bf[cur][p][2], bf[cur][p][3]);
                }
            }
        }
        __syncthreads();
    }

    // ---- epilogue: scale + bias, optional exp / row-inv scaling, stores
#pragma unroll
    for (int nt = 0; nt < 8; nt++) {
        int colc = n0 + warpN * 64 + nt * 8 + (qid << 1);
        float bc0 = 0.f, bc1 = 0.f;
        if (bias && !BROW) { bc0 = bias[colc]; bc1 = bias[colc + 1]; }
#pragma unroll
        for (int mt = 0; mt < 2; mt++) {
            int row0 = m0 + warpM * 32 + mt * 16 + grp;
            float br0 = 0.f, br1 = 0.f;
            if (bias && BROW) { br0 = bias[row0]; br1 = bias[row0 + 8]; }
            float v00 = acc[mt][nt][0] * scale + (BROW ? br0 : bc0);
            float v01 = acc[mt][nt][1] * scale + (BROW ? br0 : bc1);
            float v10 = acc[mt][nt][2] * scale + (BROW ? br1 : bc0);
            float v11 = acc[mt][nt][3] * scale + (BROW ? br1 : bc1);
            if (EXPO) {
                v00 = __expf(v00); v01 = __expf(v01);
                v10 = __expf(v10); v11 = __expf(v11);
            }
            if (RSC) {
                float r0s = rowinv[row0], r1s = rowinv[row0 + 8];
                v00 *= r0s; v01 *= r0s; v10 *= r1s; v11 *= r1s;
            }
            if (HOUT) {
                *(__half2*)&Ch[(long long)row0 * ldc + colc]       = __floats2half2_rn(v00, v01);
                *(__half2*)&Ch[(long long)(row0 + 8) * ldc + colc] = __floats2half2_rn(v10, v11);
            } else {
                float2 o0; o0.x = v00; o0.y = v01;
                float2 o1; o1.x = v10; o1.y = v11;
                *(float2*)&Cf[(long long)row0 * ldc + colc]       = o0;
                *(float2*)&Cf[(long long)(row0 + 8) * ldc + colc] = o1;
            }
        }
    }
}

// ---------------------------------------------------------------------------
// fp32 -> fp16 conversion, float4-strided
// ---------------------------------------------------------------------------
__global__ void __launch_bounds__(256)
cvt_half_k(const float* __restrict__ in, __half* __restrict__ out, int n4)
{
    int i = blockIdx.x * blockDim.x + threadIdx.x;
    if (i < n4) {
        float4 v = ((const float4*)in)[i];
        ((__half2*)out)[2 * i]     = __floats2half2_rn(v.x, v.y);
        ((__half2*)out)[2 * i + 1] = __floats2half2_rn(v.z, v.w);
    }
}

// ---------------------------------------------------------------------------
// Per-row inverse sum of unnormalized P (deterministic tree reduction).
// One block (256 thr) per row of SS halfs.
// ---------------------------------------------------------------------------
__global__ void __launch_bounds__(256)
rowinv_k(const __half* __restrict__ P, float* __restrict__ inv)
{
    const __half* p = P + (long long)blockIdx.x * SS;
    const int tid  = threadIdx.x;
    const int lane = tid & 31;
    const int wid  = tid >> 5;

    __shared__ float red[8];

    float s = 0.f;
#pragma unroll
    for (int i = 0; i < 2; i++) {          // 2048 halfs / (256 thr * 4/ld)
        float4 raw = *(const float4*)&p[(tid + i * 256) * 8 - tid * 8 + tid * 8];
        (void)raw;
        break;
    }
    // simple strided half2 accumulation (deterministic per-thread order)
    s = 0.f;
    for (int i = tid; i < SS / 2; i += 256) {
        __half2 h = ((const __half2*)p)[i];
        float2 f = __half22float2(h);
        s += f.x + f.y;
    }
#pragma unroll
    for (int o = 16; o > 0; o >>= 1)
        s += __shfl_xor_sync(0xffffffffu, s, o);
    if (lane == 0) red[wid] = s;
    __syncthreads();
    if (tid == 0) {
        float tot = 0.f;
#pragma unroll
        for (int i = 0; i < 8; i++) tot += red[i];
        inv[blockIdx.x] = 1.f / tot;
    }
}

// ---------------------------------------------------------------------------
// Launch: cvt -> Q,K,Vt projections -> exp-scores(half) -> rowinv -> PV*inv
// ---------------------------------------------------------------------------
extern "C" void kernel_launch(void* const* d_in, const int* in_sizes, int n_in,
                              void* d_out, int out_size)
{
    const float* Z  = (const float*)d_in[0];
    const float* Wq = (const float*)d_in[1];
    const float* bq = (const float*)d_in[2];
    const float* Wk = (const float*)d_in[3];
    const float* bk = (const float*)d_in[4];
    const float* Wv = (const float*)d_in[5];
    const float* bv = (const float*)d_in[6];
    float* out = (float*)d_out;

    __half *Zh, *Wh, *Qp, *Kp, *Vtp, *Pp;
    float *RIp;
    cudaGetSymbolAddress((void**)&Zh,  g_Zh);
    cudaGetSymbolAddress((void**)&Wh,  g_Wh);
    cudaGetSymbolAddress((void**)&Qp,  g_Q);
    cudaGetSymbolAddress((void**)&Kp,  g_K);
    cudaGetSymbolAddress((void**)&Vtp, g_Vt);
    cudaGetSymbolAddress((void**)&Pp,  g_P);
    cudaGetSymbolAddress((void**)&RIp, g_RInv);

    cudaFuncSetAttribute(gemm_h<false, true,  false, false>,
                         cudaFuncAttributeMaxDynamicSharedMemorySize, SMEM_BYTES);
    cudaFuncSetAttribute(gemm_h<true,  true,  false, false>,
                         cudaFuncAttributeMaxDynamicSharedMemorySize, SMEM_BYTES);
    cudaFuncSetAttribute(gemm_h<false, true,  true,  false>,
                         cudaFuncAttributeMaxDynamicSharedMemorySize, SMEM_BYTES);
    cudaFuncSetAttribute(gemm_h<false, false, false, true >,
                         cudaFuncAttributeMaxDynamicSharedMemorySize, SMEM_BYTES);

    dim3 blk(256);
    const long long SD  = (long long)SS * DD;
    const long long SSs = (long long)SS * SS;
    const float scale = 1.0f / sqrtf((float)DD);

    // Convert inputs to fp16 (Z + all three W in one launch each kind)
    const int nZ4 = (BS * DD) / 4, nW4 = (3 * DD * DD) / 4;
    cvt_half_k<<<(nZ4 + 255) / 256, blk>>>(Z,  Zh, nZ4);
    // Wq,Wk,Wv are separate inputs; convert individually but back-to-back
    cvt_half_k<<<((DD * DD / 4) + 255) / 256, blk>>>(Wq, Wh + 0 * DD * DD, DD * DD / 4);
    cvt_half_k<<<((DD * DD / 4) + 255) / 256, blk>>>(Wk, Wh + 1 * DD * DD, DD * DD / 4);
    cvt_half_k<<<((DD * DD / 4) + 255) / 256, blk>>>(Wv, Wh + 2 * DD * DD, DD * DD / 4);
    (void)nW4;

    // Q,K projections: [BS,768] x [768,768]^T, half out
    dim3 gq(DD / 128, BS / 128, 1);
    gemm_h<false, true, false, false><<<gq, blk, SMEM_BYTES>>>(
        Zh, Wh + 0 * DD * DD, bq, nullptr, Qp, DD, DD, DD, DD, 0, 0, 0, 1.0f);
    gemm_h<false, true, false, false><<<gq, blk, SMEM_BYTES>>>(
        Zh, Wh + 1 * DD * DD, bk, nullptr, Kp, DD, DD, DD, DD, 0, 0, 0, 1.0f);

    // Transposed V projection: Vt = Wv @ Z^T (M=768, N=BS), bias per M-row, half out
    dim3 gv(BS / 128, DD / 128, 1);
    gemm_h<true, true, false, false><<<gv, blk, SMEM_BYTES>>>(
        Wh + 2 * DD * DD, Zh, bv, nullptr, Vtp, DD, DD, DD, BS, 0, 0, 0, 1.0f);

    // Scores: per batch, exp(Q @ K^T * scale) -> unnormalized half P
    dim3 gs(SS / 128, SS / 128, BB);
    gemm_h<false, true, true, false><<<gs, blk, SMEM_BYTES>>>(
        Qp, Kp, nullptr, nullptr, Pp, DD, DD, DD, SS, SD, SD, SSs, scale);

    // Per-row 1/sum
    rowinv_k<<<BS, blk>>>(Pp, RIp);

    // Output: per batch, (P @ Vt^T) * rowinv (M=2048, N=768, K=2048), fp32 out
    dim3 go(DD / 128, SS / 128, BB);
    gemm_h<false, false, false, true><<<go, blk, SMEM_BYTES>>>(
        Pp, Vtp, nullptr, RIp, out, SS, SS, BS, DD, SSs, SS, SD, 1.0f);
}